// round 9
// baseline (speedup 1.0000x reference)
#include <cuda_runtime.h>
#include <math.h>
#include <stdint.h>

// ---------------- problem constants ----------------
#define HIDC  256
#define NHEAD 8
#define NN1   60
#define NN2   240
#define NN3   300
#define LLAB  600
#define DHH   32
#define BBAT  32
#define SSEQ  512
#define DBERT 768
#define NSPLIT 64

#define ATTN_SMEM (32 * 601 * 4)
// fused_pool smem: P 64x520 + A 64x264 + B 2x3072 + tok 512  (floats)
#define POOL_SMEM ((64 * 520 + 64 * 264 + 2 * 3072 + 512) * 4)

// ---------------- device scratch ----------------
__device__ float g_text_enc[BBAT * SSEQ * HIDC];
__device__ float g_le      [LLAB * HIDC];
__device__ float g_Kb      [LLAB * HIDC];
__device__ float g_PAQ     [LLAB * HIDC];
__device__ float g_PMV     [LLAB * HIDC];
__device__ float g_M       [LLAB * HIDC];
__device__ float g_feat    [BBAT * LLAB * HIDC];
__device__ float g_part    [NSPLIT * BBAT * LLAB];
__device__ float g_WQe     [3 * HIDC * HIDC];
__device__ float g_WVe     [3 * HIDC * HIDC];

static inline int cdiv(int a, int b) { return (a + b - 1) / b; }

// =====================================================================
// helpers
// =====================================================================
__device__ __forceinline__ uint32_t f2tf(float x) {
    uint32_t r;
    asm("cvt.rna.tf32.f32 %0, %1;" : "=r"(r) : "f"(x));
    return r;
}

__device__ __forceinline__ void mma_tf32(float* c, const uint32_t* a, const uint32_t* b) {
    asm("mma.sync.aligned.m16n8k8.row.col.f32.tf32.tf32.f32 "
        "{%0,%1,%2,%3}, {%4,%5,%6,%7}, {%8,%9}, {%0,%1,%2,%3};"
        : "+f"(c[0]), "+f"(c[1]), "+f"(c[2]), "+f"(c[3])
        : "r"(a[0]), "r"(a[1]), "r"(a[2]), "r"(a[3]), "r"(b[0]), "r"(b[1]));
}

__device__ __forceinline__ void cpa16(void* s, const void* g, bool v) {
    uint32_t sa = (uint32_t)__cvta_generic_to_shared(s);
    int sz = v ? 16 : 0;
    asm volatile("cp.async.cg.shared.global [%0], [%1], 16, %2;" :: "r"(sa), "l"(g), "r"(sz));
}
__device__ __forceinline__ void cp_commit() { asm volatile("cp.async.commit_group;"); }
__device__ __forceinline__ void cp_wait1()  { asm volatile("cp.async.wait_group 1;"); }
__device__ __forceinline__ void cp_wait0()  { asm volatile("cp.async.wait_group 0;"); }

// =====================================================================
// 2-stage cp.async pipelined tf32 GEMM (device body)
// MODE 0: Y = acc (+bias[n]) ; MODE 1: Y = tanh(acc+bias) ; MODE 2: Y = tanh(acc)+res
// TRANS_W=false: Y[m,n]=sum_k X[m,k]*W[n,k] ; true: W[k,n]
// =====================================================================
template<int BM, int BN, int BK, int WM, int WN, int MODE, bool TRANS_W>
__device__ __forceinline__ void tgemm_dev(
    const float* __restrict__ X, const float* __restrict__ W,
    const float* __restrict__ bias, const float* __restrict__ res,
    float* __restrict__ Y,
    int M, int N, int K, int ldx, int ldw, int ldy)
{
    constexpr int NWARP = (BM / WM) * (BN / WN);
    constexpr int NTHR  = NWARP * 32;
    constexpr int LDA   = BK + 4;
    constexpr int LDBN  = BK + 4;
    constexpr int LDBT  = BN + 8;
    constexpr int MI = WM / 16, NI = WN / 8;

    __shared__ float As[2][BM * LDA];
    __shared__ float Bs[2][TRANS_W ? (BK * LDBT) : (BN * LDBN)];

    const int m0 = blockIdx.y * BM, n0 = blockIdx.x * BN;
    const int tid  = threadIdx.x;
    const int lane = tid & 31, wid = tid >> 5;
    const int wN = wid % (BN / WN), wM = wid / (BN / WN);
    const int g = lane >> 2, tg = lane & 3;

    float acc[MI][NI][4];
    #pragma unroll
    for (int i = 0; i < MI; i++)
        #pragma unroll
        for (int j = 0; j < NI; j++)
            #pragma unroll
            for (int r = 0; r < 4; r++) acc[i][j][r] = 0.f;

    const int T = K / BK;

    auto load_tile = [&](int t, int st) {
        int k0 = t * BK;
        #pragma unroll
        for (int c = tid; c < BM * (BK / 4); c += NTHR) {
            int row = c >> 2, kq = (c & 3) * 4;
            bool v = (m0 + row) < M;
            int gr = v ? (m0 + row) : 0;
            cpa16(&As[st][row * LDA + kq], X + (long)gr * ldx + k0 + kq, v);
        }
        if (!TRANS_W) {
            #pragma unroll
            for (int c = tid; c < BN * (BK / 4); c += NTHR) {
                int row = c >> 2, kq = (c & 3) * 4;
                bool v = (n0 + row) < N;
                int gr = v ? (n0 + row) : 0;
                cpa16(&Bs[st][row * LDBN + kq], W + (long)gr * ldw + k0 + kq, v);
            }
        } else {
            #pragma unroll
            for (int c = tid; c < BK * (BN / 4); c += NTHR) {
                int k = c / (BN / 4), nq = (c % (BN / 4)) * 4;
                bool v = (n0 + nq) < N;
                int gc = v ? (n0 + nq) : 0;
                cpa16(&Bs[st][k * LDBT + nq], W + (long)(k0 + k) * ldw + gc, v);
            }
        }
    };

    load_tile(0, 0);
    cp_commit();

    for (int t = 0; t < T; t++) {
        int cur = t & 1;
        if (t + 1 < T) {
            load_tile(t + 1, cur ^ 1);
            cp_commit();
            cp_wait1();
        } else {
            cp_wait0();
        }
        __syncthreads();

        #pragma unroll
        for (int kk = 0; kk < BK; kk += 8) {
            uint32_t a[MI][4], b[NI][2];
            #pragma unroll
            for (int mi = 0; mi < MI; mi++) {
                int mr = wM * WM + mi * 16;
                a[mi][0] = f2tf(As[cur][(mr + g)     * LDA + kk + tg]);
                a[mi][1] = f2tf(As[cur][(mr + g + 8) * LDA + kk + tg]);
                a[mi][2] = f2tf(As[cur][(mr + g)     * LDA + kk + tg + 4]);
                a[mi][3] = f2tf(As[cur][(mr + g + 8) * LDA + kk + tg + 4]);
            }
            #pragma unroll
            for (int ni = 0; ni < NI; ni++) {
                int nc = wN * WN + ni * 8;
                if (!TRANS_W) {
                    b[ni][0] = f2tf(Bs[cur][(nc + g) * LDBN + kk + tg]);
                    b[ni][1] = f2tf(Bs[cur][(nc + g) * LDBN + kk + tg + 4]);
                } else {
                    b[ni][0] = f2tf(Bs[cur][(kk + tg)     * LDBT + nc + g]);
                    b[ni][1] = f2tf(Bs[cur][(kk + tg + 4) * LDBT + nc + g]);
                }
            }
            #pragma unroll
            for (int mi = 0; mi < MI; mi++)
                #pragma unroll
                for (int ni = 0; ni < NI; ni++)
                    mma_tf32(acc[mi][ni], a[mi], b[ni]);
        }
        __syncthreads();
    }

    #pragma unroll
    for (int mi = 0; mi < MI; mi++) {
        #pragma unroll
        for (int ni = 0; ni < NI; ni++) {
            int mr = m0 + wM * WM + mi * 16 + g;
            int nc = n0 + wN * WN + ni * 8 + 2 * tg;
            #pragma unroll
            for (int r = 0; r < 4; r++) {
                int m = mr + (r >> 1) * 8;
                int n = nc + (r & 1);
                if (m >= M || n >= N) continue;
                float v = acc[mi][ni][r];
                if (MODE == 0)      { if (bias) v += bias[n]; }
                else if (MODE == 1) { v = tanhf(v + bias[n]); }
                else if (MODE == 2) { v = tanhf(v) + res[(long)m * ldy + n]; }
                Y[(long)m * ldy + n] = v;
            }
        }
    }
}

template<int BM, int BN, int BK, int WM, int WN, int MODE, bool TRANS_W>
__global__ void __launch_bounds__((BM / WM) * (BN / WN) * 32)
tgemm_g(const float* __restrict__ Xg, const float* __restrict__ Wg,
        const float* __restrict__ bias, float* __restrict__ Yg,
        int M, int N, int K, int ldx, int ldw, int ldy,
        long bsx, long bsw, long bsy)
{
    int bz = blockIdx.z;
    tgemm_dev<BM, BN, BK, WM, WN, MODE, TRANS_W>(
        Xg + bz * bsx, Wg + bz * bsw, bias, nullptr, Yg + bz * bsy,
        M, N, K, ldx, ldw, ldy);
}

// =====================================================================
// Effective weights
// =====================================================================
__global__ void prep_eff(const float* __restrict__ WQ, const float* __restrict__ WV,
                         const float* __restrict__ PA, const float* __restrict__ PM,
                         float* __restrict__ WQe, float* __restrict__ WVe)
{
    int t = blockIdx.x >> 3, h = blockIdx.x & 7;
    const float* W = (blockIdx.y == 0 ? WQ : WV) + (long)t * HIDC * HIDC + (long)h * DHH * HIDC;
    const float* P = (blockIdx.y == 0 ? PA : PM);
    float* O = (blockIdx.y == 0 ? WQe : WVe) + (long)t * HIDC * HIDC + (long)h * DHH * HIDC;

    __shared__ float Ps[DHH][DHH];
    int tid = threadIdx.x;
    for (int i = tid; i < DHH * DHH; i += 256) Ps[i / DHH][i % DHH] = P[i];
    __syncthreads();

    int c = tid;
    float w[DHH];
    #pragma unroll
    for (int d = 0; d < DHH; d++) w[d] = W[(long)d * HIDC + c];
    #pragma unroll
    for (int e = 0; e < DHH; e++) {
        float s = 0.f;
        #pragma unroll
        for (int d = 0; d < DHH; d++) s += Ps[e][d] * w[d];
        O[(long)e * HIDC + c] = s;
    }
}

// =====================================================================
// Fused per-type projections: grid (4, 5, 9), 128 threads
// =====================================================================
__global__ void __launch_bounds__(128)
proj_fused(const float* __restrict__ le,
           const float* __restrict__ WK,
           const float* __restrict__ WQe,
           const float* __restrict__ WVe,
           float* __restrict__ Kb, float* __restrict__ PAQ,
           float* __restrict__ PMV)
{
    int z = blockIdx.z;
    int t = z % 3, which = z / 3;
    int s0 = (t == 0) ? 0 : (t == 1 ? NN1 : NN1 + NN2);
    int cnt = (t == 0) ? NN1 : (t == 1 ? NN2 : NN3);
    if ((int)blockIdx.y * 64 >= cnt) return;
    const float* W = (which == 0 ? WK : (which == 1 ? WQe : WVe)) + (long)t * HIDC * HIDC;
    float* Y = (which == 0 ? Kb : (which == 1 ? PAQ : PMV)) + (long)s0 * HIDC;
    tgemm_dev<64, 64, 16, 32, 32, 0, false>(
        le + (long)s0 * HIDC, W, nullptr, nullptr, Y,
        cnt, HIDC, HIDC, HIDC, HIDC, HIDC);
}

__global__ void __launch_bounds__(128)
wa_fused(const float* __restrict__ Mm, const float* __restrict__ WA,
         float* __restrict__ le)
{
    int t = blockIdx.z;
    int s0 = (t == 0) ? 0 : (t == 1 ? NN1 : NN1 + NN2);
    int cnt = (t == 0) ? NN1 : (t == 1 ? NN2 : NN3);
    if ((int)blockIdx.y * 64 >= cnt) return;
    tgemm_dev<64, 64, 16, 32, 32, 2, false>(
        Mm + (long)s0 * HIDC, WA + (long)t * HIDC * HIDC, nullptr,
        le + (long)s0 * HIDC, le + (long)s0 * HIDC,
        cnt, HIDC, HIDC, HIDC, HIDC, HIDC);
}

// =====================================================================
// Fused HGT attention (unchanged from R5)
// =====================================================================
__global__ void __launch_bounds__(256)
attn_fused(const float* __restrict__ paq, const float* __restrict__ Kb,
           const float* __restrict__ pmv, const int* __restrict__ amask,
           float* __restrict__ Mout)
{
    extern __shared__ float Ss[];
    __shared__ float invs[32];
    const float scale = 0.17677669529663687f;

    const int qt = blockIdx.x, h = blockIdx.y;
    const int q0 = qt * 32, hd = h * DHH;
    const int tid = threadIdx.x, lane = tid & 31, wid = tid >> 5;

    {
        int gq = q0 + lane;
        int qc = (gq < LLAB) ? gq : (LLAB - 1);
        float qreg[DHH];
        #pragma unroll
        for (int d = 0; d < DHH; d++) qreg[d] = paq[(long)qc * HIDC + hd + d];

        int kend = wid * 75 + 75;
        for (int k = wid * 75; k < kend; k++) {
            float kv = Kb[(long)k * HIDC + hd + lane];
            float s = 0.f;
            #pragma unroll
            for (int d = 0; d < DHH; d++)
                s = fmaf(qreg[d], __shfl_sync(0xffffffffu, kv, d), s);
            Ss[lane * 601 + k] = s;
        }
    }
    __syncthreads();

    #pragma unroll
    for (int rr = 0; rr < 4; rr++) {
        int q = wid * 4 + rr;
        int gq = q0 + q;
        if (gq >= LLAB) continue;
        bool qb1 = (gq < NN1), qb3 = (gq >= NN1 + NN2);

        float mx = -INFINITY;
        for (int k = lane; k < LLAB; k += 32) {
            bool kb1 = (k < NN1), kb3 = (k >= NN1 + NN2);
            bool Z = (qb1 && kb3) || (qb3 && kb1);
            float mk = (amask[(long)gq * LLAB + k] == 0) ? -INFINITY : 0.f;
            float v = (Z ? 0.f : Ss[q * 601 + k] * scale) + mk;
            Ss[q * 601 + k] = v;
            mx = fmaxf(mx, v);
        }
        #pragma unroll
        for (int o = 16; o; o >>= 1) mx = fmaxf(mx, __shfl_xor_sync(0xffffffffu, mx, o));

        float sum = 0.f;
        for (int k = lane; k < LLAB; k += 32) {
            bool kb1 = (k < NN1), kb3 = (k >= NN1 + NN2);
            bool Z = (qb1 && kb3) || (qb3 && kb1);
            float e = expf(Ss[q * 601 + k] - mx);
            sum += e;
            Ss[q * 601 + k] = Z ? 0.f : e;
        }
        #pragma unroll
        for (int o = 16; o; o >>= 1) sum += __shfl_xor_sync(0xffffffffu, sum, o);
        if (lane == 0) invs[q] = 1.f / sum;
    }
    __syncthreads();

    {
        float acc0 = 0.f, acc1 = 0.f, acc2 = 0.f, acc3 = 0.f;
        const int qb = wid * 4;
        for (int k = 0; k < LLAB; k += 2) {
            float pv0 = pmv[(long)k * HIDC + hd + lane];
            float pv1 = pmv[(long)(k + 1) * HIDC + hd + lane];
            acc0 = fmaf(Ss[(qb + 0) * 601 + k], pv0, acc0);
            acc1 = fmaf(Ss[(qb + 1) * 601 + k], pv0, acc1);
            acc2 = fmaf(Ss[(qb + 2) * 601 + k], pv0, acc2);
            acc3 = fmaf(Ss[(qb + 3) * 601 + k], pv0, acc3);
            acc0 = fmaf(Ss[(qb + 0) * 601 + k + 1], pv1, acc0);
            acc1 = fmaf(Ss[(qb + 1) * 601 + k + 1], pv1, acc1);
            acc2 = fmaf(Ss[(qb + 2) * 601 + k + 1], pv1, acc2);
            acc3 = fmaf(Ss[(qb + 3) * 601 + k + 1], pv1, acc3);
        }
        float accs[4] = {acc0, acc1, acc2, acc3};
        #pragma unroll
        for (int rr = 0; rr < 4; rr++) {
            int gq = q0 + qb + rr;
            if (gq < LLAB)
                Mout[(long)gq * HIDC + hd + lane] = accs[rr] * invs[qb + rr];
        }
    }
}

// =====================================================================
// Fused pooling: logits = le_tile @ te[b]^T  -> pad-masked softmax over S
//                -> feat = P @ te[b].   One block per (64-label tile, batch).
// grid (10, 32), 256 threads (8 warps: 2 x 4 warptiles of 32x64).
// =====================================================================
__global__ void __launch_bounds__(256)
fused_pool(const float* __restrict__ le, const float* __restrict__ te,
           const int* __restrict__ tok, float* __restrict__ feat)
{
    extern __shared__ float sm[];
    float* P  = sm;                       // 64 x 520 logits/probs
    float* A  = sm + 64 * 520;            // 64 x 264 le tile
    float* Bb = A + 64 * 264;             // 2 stages x 3072
    int*   Tk = (int*)(Bb + 2 * 3072);    // 512 tokens

    const int l0 = blockIdx.x * 64;
    const int b  = blockIdx.y;
    const int tid = threadIdx.x, lane = tid & 31, wid = tid >> 5;
    const int wN = wid & 3, wM = wid >> 2;
    const int g = lane >> 2, tg = lane & 3;
    const float* teb = te + (long)b * SSEQ * HIDC;

    if (tid < 128) ((int4*)Tk)[tid] = ((const int4*)(tok + (long)b * SSEQ))[tid];

    // le tile -> A[m*264 + k]  (zero-padded rows past LLAB)
    for (int u = tid; u < 64 * 64; u += 256) {
        int row = u >> 6, c = (u & 63) * 4;
        bool v = (l0 + row) < LLAB;
        cpa16(&A[row * 264 + c], le + (long)(v ? (l0 + row) : 0) * HIDC + c, v);
    }
    cp_commit();

    // ---------- phase A: logits, two N-halves of 256 s-columns ----------
    for (int hf = 0; hf < 2; hf++) {
        if (hf) __syncthreads();
        for (int u = tid; u < 512; u += 256) {           // tile 0 prefetch
            int n = u >> 1, c4 = (u & 1) * 4;
            cpa16(&Bb[n * 12 + c4], teb + (long)(hf * 256 + n) * HIDC + c4, true);
        }
        cp_commit();

        float acc[2][8][4] = {};
        for (int t = 0; t < 32; t++) {
            int cur = t & 1;
            if (t + 1 < 32) {
                int k0 = (t + 1) * 8;
                for (int u = tid; u < 512; u += 256) {
                    int n = u >> 1, c4 = (u & 1) * 4;
                    cpa16(&Bb[(cur ^ 1) * 3072 + n * 12 + c4],
                          teb + (long)(hf * 256 + n) * HIDC + k0 + c4, true);
                }
                cp_commit();
                cp_wait1();
            } else cp_wait0();
            __syncthreads();

            uint32_t a[2][4], bf[8][2];
            #pragma unroll
            for (int mi = 0; mi < 2; mi++) {
                int mr = wM * 32 + mi * 16;
                a[mi][0] = f2tf(A[(mr + g)     * 264 + t * 8 + tg]);
                a[mi][1] = f2tf(A[(mr + g + 8) * 264 + t * 8 + tg]);
                a[mi][2] = f2tf(A[(mr + g)     * 264 + t * 8 + tg + 4]);
                a[mi][3] = f2tf(A[(mr + g + 8) * 264 + t * 8 + tg + 4]);
            }
            #pragma unroll
            for (int ni = 0; ni < 8; ni++) {
                int nc = wN * 64 + ni * 8;
                bf[ni][0] = f2tf(Bb[cur * 3072 + (nc + g) * 12 + tg]);
                bf[ni][1] = f2tf(Bb[cur * 3072 + (nc + g) * 12 + tg + 4]);
            }
            #pragma unroll
            for (int mi = 0; mi < 2; mi++)
                #pragma unroll
                for (int ni = 0; ni < 8; ni++)
                    mma_tf32(acc[mi][ni], a[mi], bf[ni]);
            __syncthreads();
        }

        // store logits with pad mask
        #pragma unroll
        for (int mi = 0; mi < 2; mi++)
            #pragma unroll
            for (int ni = 0; ni < 8; ni++)
                #pragma unroll
                for (int r = 0; r < 4; r++) {
                    int m = wM * 32 + mi * 16 + g + (r >> 1) * 8;
                    int n = wN * 64 + ni * 8 + 2 * tg + (r & 1);
                    int s = hf * 256 + n;
                    int tv = Tk[s];
                    bool bad = (tv == 0) || (tv == 101) || (tv == 102);
                    P[m * 520 + s] = acc[mi][ni][r] + (bad ? -INFINITY : 0.f);
                }
    }
    __syncthreads();

    // ---------- softmax over 512 per row (warp = 8 rows) ----------
    #pragma unroll
    for (int rr = 0; rr < 8; rr++) {
        int m = wid * 8 + rr;
        float mx = -INFINITY;
        #pragma unroll
        for (int i = 0; i < 16; i++) mx = fmaxf(mx, P[m * 520 + lane + i * 32]);
        #pragma unroll
        for (int o = 16; o; o >>= 1) mx = fmaxf(mx, __shfl_xor_sync(0xffffffffu, mx, o));
        float e[16], sum = 0.f;
        #pragma unroll
        for (int i = 0; i < 16; i++) {
            e[i] = expf(P[m * 520 + lane + i * 32] - mx);
            sum += e[i];
        }
        #pragma unroll
        for (int o = 16; o; o >>= 1) sum += __shfl_xor_sync(0xffffffffu, sum, o);
        float inv = 1.f / sum;
        #pragma unroll
        for (int i = 0; i < 16; i++) P[m * 520 + lane + i * 32] = e[i] * inv;
    }
    __syncthreads();

    // ---------- phase B: feat = P[64,512] @ te[b][512,256] ----------
    {
        float acc[2][8][4] = {};
        for (int u = tid; u < 512; u += 256) {           // tile 0 prefetch
            int k = u >> 6, c = (u & 63) * 4;
            cpa16(&Bb[k * 264 + c], teb + (long)k * HIDC + c, true);
        }
        cp_commit();

        for (int t = 0; t < 64; t++) {
            int cur = t & 1;
            if (t + 1 < 64) {
                int k0 = (t + 1) * 8;
                for (int u = tid; u < 512; u += 256) {
                    int k = u >> 6, c = (u & 63) * 4;
                    cpa16(&Bb[(cur ^ 1) * 3072 + k * 264 + c],
                          teb + (long)(k0 + k) * HIDC + c, true);
                }
                cp_commit();
                cp_wait1();
            } else cp_wait0();
            __syncthreads();

            uint32_t a[2][4], bf[8][2];
            #pragma unroll
            for (int mi = 0; mi < 2; mi++) {
                int mr = wM * 32 + mi * 16;
                a[mi][0] = f2tf(P[(mr + g)     * 520 + t * 8 + tg]);
                a[mi][1] = f2tf(P[(mr + g + 8) * 520 + t * 8 + tg]);
                a[mi][2] = f2tf(P[(mr + g)     * 520 + t * 8 + tg + 4]);
                a[mi][3] = f2tf(P[(mr + g + 8) * 520 + t * 8 + tg + 4]);
            }
            #pragma unroll
            for (int ni = 0; ni < 8; ni++) {
                int nc = wN * 64 + ni * 8;
                bf[ni][0] = f2tf(Bb[cur * 3072 + tg * 264 + nc + g]);
                bf[ni][1] = f2tf(Bb[cur * 3072 + (tg + 4) * 264 + nc + g]);
            }
            #pragma unroll
            for (int mi = 0; mi < 2; mi++)
                #pragma unroll
                for (int ni = 0; ni < 8; ni++)
                    mma_tf32(acc[mi][ni], a[mi], bf[ni]);
            __syncthreads();
        }

        #pragma unroll
        for (int mi = 0; mi < 2; mi++)
            #pragma unroll
            for (int ni = 0; ni < 8; ni++)
                #pragma unroll
                for (int r = 0; r < 4; r++) {
                    int m = wM * 32 + mi * 16 + g + (r >> 1) * 8;
                    int n = wN * 64 + ni * 8 + 2 * tg + (r & 1);
                    int gl = l0 + m;
                    if (gl < LLAB)
                        feat[((long)b * LLAB + gl) * HIDC + n] = acc[mi][ni][r];
                }
    }
}

// ---------------- final split-K reduce + sigmoid ----------------
__global__ void final_reduce(const float* __restrict__ part,
                             const float* __restrict__ bout,
                             float* __restrict__ out)
{
    int i = blockIdx.x * blockDim.x + threadIdx.x;
    if (i >= BBAT * LLAB) return;
    int l = i % LLAB;
    float s = bout[l];
    #pragma unroll
    for (int z = 0; z < NSPLIT; z++) s += part[z * (BBAT * LLAB) + i];
    out[i] = 1.f / (1.f + expf(-s));
}

// ---------------- streams for overlap (created at static init) ----------------
struct HgtStreams {
    cudaStream_t s_te = nullptr;
    cudaEvent_t ev_fork = nullptr, ev_te = nullptr;
    HgtStreams() {
        if (cudaStreamCreateWithFlags(&s_te, cudaStreamNonBlocking) != cudaSuccess) { s_te = nullptr; return; }
        if (cudaEventCreateWithFlags(&ev_fork, cudaEventDisableTiming) != cudaSuccess) { s_te = nullptr; return; }
        if (cudaEventCreateWithFlags(&ev_te, cudaEventDisableTiming) != cudaSuccess) { s_te = nullptr; return; }
    }
};
static HgtStreams g_hs;

// ---------------- host orchestration ----------------
extern "C" void kernel_launch(void* const* d_in, const int* in_sizes, int n_in,
                              void* d_out, int out_size)
{
    const int*   inputs      = (const int*)  d_in[0];
    const float* text_hidden = (const float*)d_in[1];
    const float* label_feat  = (const float*)d_in[2];
    const int*   amask       = (const int*)  d_in[3];
    const float* Wt   = (const float*)d_in[4];
    const float* bt   = (const float*)d_in[5];
    const float* Wl   = (const float*)d_in[6];
    const float* bl   = (const float*)d_in[7];
    const float* WK   = (const float*)d_in[8];
    const float* WQ   = (const float*)d_in[9];
    const float* WV   = (const float*)d_in[10];
    const float* PA   = (const float*)d_in[11];
    const float* PM   = (const float*)d_in[12];
    const float* WA   = (const float*)d_in[13];
    const float* Wout = (const float*)d_in[14];
    const float* bout = (const float*)d_in[15];
    float* out = (float*)d_out;

    float *te, *le, *Kb, *paq, *pmv, *mm, *feat, *part, *wqe, *wve;
    cudaGetSymbolAddress((void**)&te,   g_text_enc);
    cudaGetSymbolAddress((void**)&le,   g_le);
    cudaGetSymbolAddress((void**)&Kb,   g_Kb);
    cudaGetSymbolAddress((void**)&paq,  g_PAQ);
    cudaGetSymbolAddress((void**)&pmv,  g_PMV);
    cudaGetSymbolAddress((void**)&mm,   g_M);
    cudaGetSymbolAddress((void**)&feat, g_feat);
    cudaGetSymbolAddress((void**)&part, g_part);
    cudaGetSymbolAddress((void**)&wqe,  g_WQe);
    cudaGetSymbolAddress((void**)&wve,  g_WVe);

    cudaFuncSetAttribute(attn_fused, cudaFuncAttributeMaxDynamicSharedMemorySize, ATTN_SMEM);
    cudaFuncSetAttribute(fused_pool, cudaFuncAttributeMaxDynamicSharedMemorySize, POOL_SMEM);

    const bool ovl = (g_hs.s_te != nullptr);
    cudaStream_t ste = ovl ? g_hs.s_te : (cudaStream_t)0;

    // ---- fork: text_enc on side stream, label chain on main stream ----
    if (ovl) {
        cudaEventRecord(g_hs.ev_fork, 0);
        cudaStreamWaitEvent(g_hs.s_te, g_hs.ev_fork, 0);
    }

    // text_enc = tanh(text_hidden @ Wt^T + bt)   [16384, 256] K=768
    tgemm_g<128, 128, 16, 64, 32, 1, false><<<dim3(cdiv(HIDC, 128), cdiv(BBAT * SSEQ, 128), 1), 256, 0, ste>>>(
        text_hidden, Wt, bt, te,
        BBAT * SSEQ, HIDC, DBERT, DBERT, DBERT, HIDC, 0, 0, 0);
    if (ovl) cudaEventRecord(g_hs.ev_te, g_hs.s_te);

    // ---- label-side chain on main stream ----
    prep_eff<<<dim3(24, 2), 256>>>(WQ, WV, PA, PM, wqe, wve);

    tgemm_g<128, 128, 16, 64, 32, 0, false><<<dim3(cdiv(HIDC, 128), cdiv(LLAB, 128), 1), 256>>>(
        label_feat, Wl, bl, le,
        LLAB, HIDC, DBERT, DBERT, DBERT, HIDC, 0, 0, 0);

    for (int layer = 0; layer < 2; layer++) {
        proj_fused<<<dim3(cdiv(HIDC, 64), cdiv(NN3, 64), 9), 128>>>(
            le, WK, wqe, wve, Kb, paq, pmv);

        attn_fused<<<dim3(cdiv(LLAB, 32), NHEAD), 256, ATTN_SMEM>>>(
            paq, Kb, pmv, amask, mm);

        wa_fused<<<dim3(cdiv(HIDC, 64), cdiv(NN3, 64), 3), 128>>>(mm, WA, le);
    }

    // ---- join: pooling needs both le and text_enc ----
    if (ovl) cudaStreamWaitEvent(0, g_hs.ev_te, 0);

    fused_pool<<<dim3(cdiv(LLAB, 64), BBAT), 256, POOL_SMEM>>>(le, te, inputs, feat);

    // final GEMM, split-K 64: M=32, N=600, K=2400/slice
    {
        const int KS = (LLAB * HIDC) / NSPLIT;   // 2400
        tgemm_g<32, 128, 16, 16, 32, 0, false><<<dim3(cdiv(LLAB, 128), 1, NSPLIT), 256>>>(
            feat, Wout, nullptr, part,
            BBAT, LLAB, KS,
            LLAB * HIDC, LLAB * HIDC, LLAB,
            (long)KS, (long)KS, (long)BBAT * LLAB);
    }

    final_reduce<<<cdiv(BBAT * LLAB, 256), 256>>>(part, bout, out);
}

// round 11
// speedup vs baseline: 1.1054x; 1.1054x over previous
#include <cuda_runtime.h>
#include <math.h>
#include <stdint.h>

// ---------------- problem constants ----------------
#define HIDC  256
#define NHEAD 8
#define NN1   60
#define NN2   240
#define NN3   300
#define LLAB  600
#define DHH   32
#define BBAT  32
#define SSEQ  512
#define DBERT 768
#define NSPLIT 64

#define ATTN_SMEM (32 * 601 * 4)

// ---------------- device scratch ----------------
__device__ float g_text_enc[BBAT * SSEQ * HIDC];
__device__ float g_le      [LLAB * HIDC];
__device__ float g_Kb      [LLAB * HIDC];
__device__ float g_PAQ     [LLAB * HIDC];
__device__ float g_PMV     [LLAB * HIDC];
__device__ float g_M       [LLAB * HIDC];
__device__ float g_aw      [BBAT * LLAB * SSEQ];
__device__ float g_feat    [BBAT * LLAB * HIDC];
__device__ float g_part    [NSPLIT * BBAT * LLAB];
__device__ float g_WQe     [3 * HIDC * HIDC];
__device__ float g_WVe     [3 * HIDC * HIDC];

static inline int cdiv(int a, int b) { return (a + b - 1) / b; }

// =====================================================================
// helpers
// =====================================================================
__device__ __forceinline__ uint32_t f2tf(float x) {
    uint32_t r;
    asm("cvt.rna.tf32.f32 %0, %1;" : "=r"(r) : "f"(x));
    return r;
}

__device__ __forceinline__ void mma_tf32(float* c, const uint32_t* a, const uint32_t* b) {
    asm("mma.sync.aligned.m16n8k8.row.col.f32.tf32.tf32.f32 "
        "{%0,%1,%2,%3}, {%4,%5,%6,%7}, {%8,%9}, {%0,%1,%2,%3};"
        : "+f"(c[0]), "+f"(c[1]), "+f"(c[2]), "+f"(c[3])
        : "r"(a[0]), "r"(a[1]), "r"(a[2]), "r"(a[3]), "r"(b[0]), "r"(b[1]));
}

__device__ __forceinline__ void cpa16(void* s, const void* g, bool v) {
    uint32_t sa = (uint32_t)__cvta_generic_to_shared(s);
    int sz = v ? 16 : 0;
    asm volatile("cp.async.cg.shared.global [%0], [%1], 16, %2;" :: "r"(sa), "l"(g), "r"(sz));
}
__device__ __forceinline__ void cp_commit() { asm volatile("cp.async.commit_group;"); }
__device__ __forceinline__ void cp_wait1()  { asm volatile("cp.async.wait_group 1;"); }
__device__ __forceinline__ void cp_wait0()  { asm volatile("cp.async.wait_group 0;"); }

// =====================================================================
// 2-stage cp.async pipelined tf32 GEMM (device body)
// MODE 0: Y = acc (+bias[n]) ; MODE 1: Y = tanh(acc+bias) ; MODE 2: Y = tanh(acc)+res
// TRANS_W=false: Y[m,n]=sum_k X[m,k]*W[n,k] ; true: W[k,n]
// =====================================================================
template<int BM, int BN, int BK, int WM, int WN, int MODE, bool TRANS_W>
__device__ __forceinline__ void tgemm_dev(
    const float* __restrict__ X, const float* __restrict__ W,
    const float* __restrict__ bias, const float* __restrict__ res,
    float* __restrict__ Y,
    int M, int N, int K, int ldx, int ldw, int ldy)
{
    constexpr int NWARP = (BM / WM) * (BN / WN);
    constexpr int NTHR  = NWARP * 32;
    constexpr int LDA   = BK + 4;
    constexpr int LDBN  = BK + 4;
    constexpr int LDBT  = BN + 8;
    constexpr int MI = WM / 16, NI = WN / 8;

    __shared__ float As[2][BM * LDA];
    __shared__ float Bs[2][TRANS_W ? (BK * LDBT) : (BN * LDBN)];

    const int m0 = blockIdx.y * BM, n0 = blockIdx.x * BN;
    const int tid  = threadIdx.x;
    const int lane = tid & 31, wid = tid >> 5;
    const int wN = wid % (BN / WN), wM = wid / (BN / WN);
    const int g = lane >> 2, tg = lane & 3;

    float acc[MI][NI][4];
    #pragma unroll
    for (int i = 0; i < MI; i++)
        #pragma unroll
        for (int j = 0; j < NI; j++)
            #pragma unroll
            for (int r = 0; r < 4; r++) acc[i][j][r] = 0.f;

    const int T = K / BK;

    auto load_tile = [&](int t, int st) {
        int k0 = t * BK;
        #pragma unroll
        for (int c = tid; c < BM * (BK / 4); c += NTHR) {
            int row = c >> 2, kq = (c & 3) * 4;
            bool v = (m0 + row) < M;
            int gr = v ? (m0 + row) : 0;
            cpa16(&As[st][row * LDA + kq], X + (long)gr * ldx + k0 + kq, v);
        }
        if (!TRANS_W) {
            #pragma unroll
            for (int c = tid; c < BN * (BK / 4); c += NTHR) {
                int row = c >> 2, kq = (c & 3) * 4;
                bool v = (n0 + row) < N;
                int gr = v ? (n0 + row) : 0;
                cpa16(&Bs[st][row * LDBN + kq], W + (long)gr * ldw + k0 + kq, v);
            }
        } else {
            #pragma unroll
            for (int c = tid; c < BK * (BN / 4); c += NTHR) {
                int k = c / (BN / 4), nq = (c % (BN / 4)) * 4;
                bool v = (n0 + nq) < N;
                int gc = v ? (n0 + nq) : 0;
                cpa16(&Bs[st][k * LDBT + nq], W + (long)(k0 + k) * ldw + gc, v);
            }
        }
    };

    load_tile(0, 0);
    cp_commit();

    for (int t = 0; t < T; t++) {
        int cur = t & 1;
        if (t + 1 < T) {
            load_tile(t + 1, cur ^ 1);
            cp_commit();
            cp_wait1();
        } else {
            cp_wait0();
        }
        __syncthreads();

        #pragma unroll
        for (int kk = 0; kk < BK; kk += 8) {
            uint32_t a[MI][4], b[NI][2];
            #pragma unroll
            for (int mi = 0; mi < MI; mi++) {
                int mr = wM * WM + mi * 16;
                a[mi][0] = f2tf(As[cur][(mr + g)     * LDA + kk + tg]);
                a[mi][1] = f2tf(As[cur][(mr + g + 8) * LDA + kk + tg]);
                a[mi][2] = f2tf(As[cur][(mr + g)     * LDA + kk + tg + 4]);
                a[mi][3] = f2tf(As[cur][(mr + g + 8) * LDA + kk + tg + 4]);
            }
            #pragma unroll
            for (int ni = 0; ni < NI; ni++) {
                int nc = wN * WN + ni * 8;
                if (!TRANS_W) {
                    b[ni][0] = f2tf(Bs[cur][(nc + g) * LDBN + kk + tg]);
                    b[ni][1] = f2tf(Bs[cur][(nc + g) * LDBN + kk + tg + 4]);
                } else {
                    b[ni][0] = f2tf(Bs[cur][(kk + tg)     * LDBT + nc + g]);
                    b[ni][1] = f2tf(Bs[cur][(kk + tg + 4) * LDBT + nc + g]);
                }
            }
            #pragma unroll
            for (int mi = 0; mi < MI; mi++)
                #pragma unroll
                for (int ni = 0; ni < NI; ni++)
                    mma_tf32(acc[mi][ni], a[mi], b[ni]);
        }
        __syncthreads();
    }

    #pragma unroll
    for (int mi = 0; mi < MI; mi++) {
        #pragma unroll
        for (int ni = 0; ni < NI; ni++) {
            int mr = m0 + wM * WM + mi * 16 + g;
            int nc = n0 + wN * WN + ni * 8 + 2 * tg;
            #pragma unroll
            for (int r = 0; r < 4; r++) {
                int m = mr + (r >> 1) * 8;
                int n = nc + (r & 1);
                if (m >= M || n >= N) continue;
                float v = acc[mi][ni][r];
                if (MODE == 0)      { if (bias) v += bias[n]; }
                else if (MODE == 1) { v = tanhf(v + bias[n]); }
                else if (MODE == 2) { v = tanhf(v) + res[(long)m * ldy + n]; }
                Y[(long)m * ldy + n] = v;
            }
        }
    }
}

template<int BM, int BN, int BK, int WM, int WN, int MODE, bool TRANS_W>
__global__ void __launch_bounds__((BM / WM) * (BN / WN) * 32)
tgemm_g(const float* __restrict__ Xg, const float* __restrict__ Wg,
        const float* __restrict__ bias, float* __restrict__ Yg,
        int M, int N, int K, int ldx, int ldw, int ldy,
        long bsx, long bsw, long bsy)
{
    int bz = blockIdx.z;
    tgemm_dev<BM, BN, BK, WM, WN, MODE, TRANS_W>(
        Xg + bz * bsx, Wg + bz * bsw, bias, nullptr, Yg + bz * bsy,
        M, N, K, ldx, ldw, ldy);
}

// =====================================================================
// Effective weights
// =====================================================================
__global__ void prep_eff(const float* __restrict__ WQ, const float* __restrict__ WV,
                         const float* __restrict__ PA, const float* __restrict__ PM,
                         float* __restrict__ WQe, float* __restrict__ WVe)
{
    int t = blockIdx.x >> 3, h = blockIdx.x & 7;
    const float* W = (blockIdx.y == 0 ? WQ : WV) + (long)t * HIDC * HIDC + (long)h * DHH * HIDC;
    const float* P = (blockIdx.y == 0 ? PA : PM);
    float* O = (blockIdx.y == 0 ? WQe : WVe) + (long)t * HIDC * HIDC + (long)h * DHH * HIDC;

    __shared__ float Ps[DHH][DHH];
    int tid = threadIdx.x;
    for (int i = tid; i < DHH * DHH; i += 256) Ps[i / DHH][i % DHH] = P[i];
    __syncthreads();

    int c = tid;
    float w[DHH];
    #pragma unroll
    for (int d = 0; d < DHH; d++) w[d] = W[(long)d * HIDC + c];
    #pragma unroll
    for (int e = 0; e < DHH; e++) {
        float s = 0.f;
        #pragma unroll
        for (int d = 0; d < DHH; d++) s += Ps[e][d] * w[d];
        O[(long)e * HIDC + c] = s;
    }
}

// =====================================================================
// Fused per-type projections: grid (4, 5, 9), 128 threads
// =====================================================================
__global__ void __launch_bounds__(128)
proj_fused(const float* __restrict__ le,
           const float* __restrict__ WK,
           const float* __restrict__ WQe,
           const float* __restrict__ WVe,
           float* __restrict__ Kb, float* __restrict__ PAQ,
           float* __restrict__ PMV)
{
    int z = blockIdx.z;
    int t = z % 3, which = z / 3;
    int s0 = (t == 0) ? 0 : (t == 1 ? NN1 : NN1 + NN2);
    int cnt = (t == 0) ? NN1 : (t == 1 ? NN2 : NN3);
    if ((int)blockIdx.y * 64 >= cnt) return;
    const float* W = (which == 0 ? WK : (which == 1 ? WQe : WVe)) + (long)t * HIDC * HIDC;
    float* Y = (which == 0 ? Kb : (which == 1 ? PAQ : PMV)) + (long)s0 * HIDC;
    tgemm_dev<64, 64, 16, 32, 32, 0, false>(
        le + (long)s0 * HIDC, W, nullptr, nullptr, Y,
        cnt, HIDC, HIDC, HIDC, HIDC, HIDC);
}

__global__ void __launch_bounds__(128)
wa_fused(const float* __restrict__ Mm, const float* __restrict__ WA,
         float* __restrict__ le)
{
    int t = blockIdx.z;
    int s0 = (t == 0) ? 0 : (t == 1 ? NN1 : NN1 + NN2);
    int cnt = (t == 0) ? NN1 : (t == 1 ? NN2 : NN3);
    if ((int)blockIdx.y * 64 >= cnt) return;
    tgemm_dev<64, 64, 16, 32, 32, 2, false>(
        Mm + (long)s0 * HIDC, WA + (long)t * HIDC * HIDC, nullptr,
        le + (long)s0 * HIDC, le + (long)s0 * HIDC,
        cnt, HIDC, HIDC, HIDC, HIDC, HIDC);
}

// =====================================================================
// Fused HGT attention
// =====================================================================
__global__ void __launch_bounds__(256)
attn_fused(const float* __restrict__ paq, const float* __restrict__ Kb,
           const float* __restrict__ pmv, const int* __restrict__ amask,
           float* __restrict__ Mout)
{
    extern __shared__ float Ss[];
    __shared__ float invs[32];
    const float scale = 0.17677669529663687f;

    const int qt = blockIdx.x, h = blockIdx.y;
    const int q0 = qt * 32, hd = h * DHH;
    const int tid = threadIdx.x, lane = tid & 31, wid = tid >> 5;

    {
        int gq = q0 + lane;
        int qc = (gq < LLAB) ? gq : (LLAB - 1);
        float qreg[DHH];
        #pragma unroll
        for (int d = 0; d < DHH; d++) qreg[d] = paq[(long)qc * HIDC + hd + d];

        int kend = wid * 75 + 75;
        for (int k = wid * 75; k < kend; k++) {
            float kv = Kb[(long)k * HIDC + hd + lane];
            float s = 0.f;
            #pragma unroll
            for (int d = 0; d < DHH; d++)
                s = fmaf(qreg[d], __shfl_sync(0xffffffffu, kv, d), s);
            Ss[lane * 601 + k] = s;
        }
    }
    __syncthreads();

    #pragma unroll
    for (int rr = 0; rr < 4; rr++) {
        int q = wid * 4 + rr;
        int gq = q0 + q;
        if (gq >= LLAB) continue;
        bool qb1 = (gq < NN1), qb3 = (gq >= NN1 + NN2);

        float mx = -INFINITY;
        for (int k = lane; k < LLAB; k += 32) {
            bool kb1 = (k < NN1), kb3 = (k >= NN1 + NN2);
            bool Z = (qb1 && kb3) || (qb3 && kb1);
            float mk = (amask[(long)gq * LLAB + k] == 0) ? -INFINITY : 0.f;
            float v = (Z ? 0.f : Ss[q * 601 + k] * scale) + mk;
            Ss[q * 601 + k] = v;
            mx = fmaxf(mx, v);
        }
        #pragma unroll
        for (int o = 16; o; o >>= 1) mx = fmaxf(mx, __shfl_xor_sync(0xffffffffu, mx, o));

        float sum = 0.f;
        for (int k = lane; k < LLAB; k += 32) {
            bool kb1 = (k < NN1), kb3 = (k >= NN1 + NN2);
            bool Z = (qb1 && kb3) || (qb3 && kb1);
            float e = expf(Ss[q * 601 + k] - mx);
            sum += e;
            Ss[q * 601 + k] = Z ? 0.f : e;
        }
        #pragma unroll
        for (int o = 16; o; o >>= 1) sum += __shfl_xor_sync(0xffffffffu, sum, o);
        if (lane == 0) invs[q] = 1.f / sum;
    }
    __syncthreads();

    {
        float acc0 = 0.f, acc1 = 0.f, acc2 = 0.f, acc3 = 0.f;
        const int qb = wid * 4;
        for (int k = 0; k < LLAB; k += 2) {
            float pv0 = pmv[(long)k * HIDC + hd + lane];
            float pv1 = pmv[(long)(k + 1) * HIDC + hd + lane];
            acc0 = fmaf(Ss[(qb + 0) * 601 + k], pv0, acc0);
            acc1 = fmaf(Ss[(qb + 1) * 601 + k], pv0, acc1);
            acc2 = fmaf(Ss[(qb + 2) * 601 + k], pv0, acc2);
            acc3 = fmaf(Ss[(qb + 3) * 601 + k], pv0, acc3);
            acc0 = fmaf(Ss[(qb + 0) * 601 + k + 1], pv1, acc0);
            acc1 = fmaf(Ss[(qb + 1) * 601 + k + 1], pv1, acc1);
            acc2 = fmaf(Ss[(qb + 2) * 601 + k + 1], pv1, acc2);
            acc3 = fmaf(Ss[(qb + 3) * 601 + k + 1], pv1, acc3);
        }
        float accs[4] = {acc0, acc1, acc2, acc3};
        #pragma unroll
        for (int rr = 0; rr < 4; rr++) {
            int gq = q0 + qb + rr;
            if (gq < LLAB)
                Mout[(long)gq * HIDC + hd + lane] = accs[rr] * invs[qb + rr];
        }
    }
}

// ---------------- pooling softmax over S with pad mask ----------------
__global__ void pool_softmax(float* __restrict__ aw, const int* __restrict__ tok)
{
    const int l = blockIdx.x, b = blockIdx.y;
    float* row = aw + ((long)b * LLAB + l) * SSEQ;
    const int* t = tok + (long)b * SSEQ;

    __shared__ float buf[SSEQ];
    __shared__ float red[33];
    const int tid = threadIdx.x;   // 256

    float mx = -INFINITY;
    for (int s = tid; s < SSEQ; s += 256) {
        int tv = t[s];
        bool bad = (tv == 0) || (tv == 101) || (tv == 102);
        float v = row[s] + (bad ? -INFINITY : 0.f);
        buf[s] = v;
        mx = fmaxf(mx, v);
    }
    for (int o = 16; o; o >>= 1) mx = fmaxf(mx, __shfl_xor_sync(0xffffffffu, mx, o));
    if ((tid & 31) == 0) red[tid >> 5] = mx;
    __syncthreads();
    if (tid < 32) {
        float v = (tid < 8) ? red[tid] : -INFINITY;
        for (int o = 16; o; o >>= 1) v = fmaxf(v, __shfl_xor_sync(0xffffffffu, v, o));
        if (tid == 0) red[32] = v;
    }
    __syncthreads();
    mx = red[32];
    __syncthreads();

    float sum = 0.f;
    for (int s = tid; s < SSEQ; s += 256) {
        float e = expf(buf[s] - mx);
        buf[s] = e;
        sum += e;
    }
    for (int o = 16; o; o >>= 1) sum += __shfl_xor_sync(0xffffffffu, sum, o);
    if ((tid & 31) == 0) red[tid >> 5] = sum;
    __syncthreads();
    if (tid < 32) {
        float v = (tid < 8) ? red[tid] : 0.f;
        for (int o = 16; o; o >>= 1) v += __shfl_xor_sync(0xffffffffu, v, o);
        if (tid == 0) red[32] = v;
    }
    __syncthreads();
    float inv = 1.f / red[32];

    for (int s = tid; s < SSEQ; s += 256) row[s] = buf[s] * inv;
}

// ---------------- final split-K reduce + sigmoid ----------------
__global__ void final_reduce(const float* __restrict__ part,
                             const float* __restrict__ bout,
                             float* __restrict__ out)
{
    int i = blockIdx.x * blockDim.x + threadIdx.x;
    if (i >= BBAT * LLAB) return;
    int l = i % LLAB;
    float s = bout[l];
    #pragma unroll
    for (int z = 0; z < NSPLIT; z++) s += part[z * (BBAT * LLAB) + i];
    out[i] = 1.f / (1.f + expf(-s));
}

// ---------------- streams for overlap (created at static init) ----------------
struct HgtStreams {
    cudaStream_t s_te = nullptr;
    cudaEvent_t ev_fork = nullptr, ev_te = nullptr;
    HgtStreams() {
        if (cudaStreamCreateWithFlags(&s_te, cudaStreamNonBlocking) != cudaSuccess) { s_te = nullptr; return; }
        if (cudaEventCreateWithFlags(&ev_fork, cudaEventDisableTiming) != cudaSuccess) { s_te = nullptr; return; }
        if (cudaEventCreateWithFlags(&ev_te, cudaEventDisableTiming) != cudaSuccess) { s_te = nullptr; return; }
    }
};
static HgtStreams g_hs;

// ---------------- host orchestration ----------------
extern "C" void kernel_launch(void* const* d_in, const int* in_sizes, int n_in,
                              void* d_out, int out_size)
{
    const int*   inputs      = (const int*)  d_in[0];
    const float* text_hidden = (const float*)d_in[1];
    const float* label_feat  = (const float*)d_in[2];
    const int*   amask       = (const int*)  d_in[3];
    const float* Wt   = (const float*)d_in[4];
    const float* bt   = (const float*)d_in[5];
    const float* Wl   = (const float*)d_in[6];
    const float* bl   = (const float*)d_in[7];
    const float* WK   = (const float*)d_in[8];
    const float* WQ   = (const float*)d_in[9];
    const float* WV   = (const float*)d_in[10];
    const float* PA   = (const float*)d_in[11];
    const float* PM   = (const float*)d_in[12];
    const float* WA   = (const float*)d_in[13];
    const float* Wout = (const float*)d_in[14];
    const float* bout = (const float*)d_in[15];
    float* out = (float*)d_out;

    float *te, *le, *Kb, *paq, *pmv, *mm, *aw, *feat, *part, *wqe, *wve;
    cudaGetSymbolAddress((void**)&te,   g_text_enc);
    cudaGetSymbolAddress((void**)&le,   g_le);
    cudaGetSymbolAddress((void**)&Kb,   g_Kb);
    cudaGetSymbolAddress((void**)&paq,  g_PAQ);
    cudaGetSymbolAddress((void**)&pmv,  g_PMV);
    cudaGetSymbolAddress((void**)&mm,   g_M);
    cudaGetSymbolAddress((void**)&aw,   g_aw);
    cudaGetSymbolAddress((void**)&feat, g_feat);
    cudaGetSymbolAddress((void**)&part, g_part);
    cudaGetSymbolAddress((void**)&wqe,  g_WQe);
    cudaGetSymbolAddress((void**)&wve,  g_WVe);

    cudaFuncSetAttribute(attn_fused, cudaFuncAttributeMaxDynamicSharedMemorySize, ATTN_SMEM);

    const bool ovl = (g_hs.s_te != nullptr);
    cudaStream_t ste = ovl ? g_hs.s_te : (cudaStream_t)0;

    // ---- fork: text_enc on side stream, label chain on main stream ----
    if (ovl) {
        cudaEventRecord(g_hs.ev_fork, 0);
        cudaStreamWaitEvent(g_hs.s_te, g_hs.ev_fork, 0);
    }

    // text_enc = tanh(text_hidden @ Wt^T + bt)   [16384, 256] K=768
    tgemm_g<128, 128, 16, 64, 32, 1, false><<<dim3(cdiv(HIDC, 128), cdiv(BBAT * SSEQ, 128), 1), 256, 0, ste>>>(
        text_hidden, Wt, bt, te,
        BBAT * SSEQ, HIDC, DBERT, DBERT, DBERT, HIDC, 0, 0, 0);
    if (ovl) cudaEventRecord(g_hs.ev_te, g_hs.s_te);

    // ---- label-side chain on main stream ----
    prep_eff<<<dim3(24, 2), 256>>>(WQ, WV, PA, PM, wqe, wve);

    tgemm_g<128, 128, 16, 64, 32, 0, false><<<dim3(cdiv(HIDC, 128), cdiv(LLAB, 128), 1), 256>>>(
        label_feat, Wl, bl, le,
        LLAB, HIDC, DBERT, DBERT, DBERT, HIDC, 0, 0, 0);

    for (int layer = 0; layer < 2; layer++) {
        proj_fused<<<dim3(cdiv(HIDC, 64), cdiv(NN3, 64), 9), 128>>>(
            le, WK, wqe, wve, Kb, paq, pmv);

        attn_fused<<<dim3(cdiv(LLAB, 32), NHEAD), 256, ATTN_SMEM>>>(
            paq, Kb, pmv, amask, mm);

        wa_fused<<<dim3(cdiv(HIDC, 64), cdiv(NN3, 64), 3), 128>>>(mm, WA, le);
    }

    // ---- join: aw needs both le and text_enc ----
    if (ovl) cudaStreamWaitEvent(0, g_hs.ev_te, 0);

    // aw[b,l,s] = le[l,:]·te[b,s,:]   [600,512] K=256, batched over b
    tgemm_g<128, 128, 16, 64, 32, 0, false><<<dim3(cdiv(SSEQ, 128), cdiv(LLAB, 128), BBAT), 256>>>(
        le, te, nullptr, aw,
        LLAB, SSEQ, HIDC, HIDC, HIDC, SSEQ,
        0, (long)SSEQ * HIDC, (long)LLAB * SSEQ);

    pool_softmax<<<dim3(LLAB, BBAT), 256>>>(aw, inputs);

    // features[b,l,e] = sum_s aw[b,l,s] * te[b,s,e]  [600,256] K=512 (NN)
    tgemm_g<128, 128, 16, 64, 32, 0, true><<<dim3(cdiv(HIDC, 128), cdiv(LLAB, 128), BBAT), 256>>>(
        aw, te, nullptr, feat,
        LLAB, HIDC, SSEQ, SSEQ, HIDC, HIDC,
        (long)LLAB * SSEQ, (long)SSEQ * HIDC, (long)LLAB * HIDC);

    // final GEMM, split-K 64: M=32, N=600, K=2400/slice
    {
        const int KS = (LLAB * HIDC) / NSPLIT;   // 2400
        tgemm_g<32, 128, 16, 16, 32, 0, false><<<dim3(cdiv(LLAB, 128), 1, NSPLIT), 256>>>(
            feat, Wout, nullptr, part,
            BBAT, LLAB, KS,
            LLAB * HIDC, LLAB * HIDC, LLAB,
            (long)KS, (long)KS, (long)BBAT * LLAB);
    }

    final_reduce<<<cdiv(BBAT * LLAB, 256), 256>>>(part, bout, out);
}

// round 13
// speedup vs baseline: 1.1507x; 1.0410x over previous
#include <cuda_runtime.h>
#include <math.h>
#include <stdint.h>

// ---------------- problem constants ----------------
#define HIDC  256
#define NHEAD 8
#define NN1   60
#define NN2   240
#define NN3   300
#define LLAB  600
#define DHH   32
#define BBAT  32
#define SSEQ  512
#define DBERT 768
#define NSPLIT 64
#define LSPLIT 300           // label split: l<300 <=> z<32
#define ZSPLIT 32

#define ATTN_SMEM (32 * 601 * 4)

// ---------------- device scratch ----------------
__device__ float g_text_enc[BBAT * SSEQ * HIDC];
__device__ float g_le      [LLAB * HIDC];
__device__ float g_Kb      [LLAB * HIDC];
__device__ float g_PAQ     [LLAB * HIDC];
__device__ float g_PMV     [LLAB * HIDC];
__device__ float g_M       [LLAB * HIDC];
__device__ float g_aw      [BBAT * LLAB * SSEQ];
__device__ float g_feat    [BBAT * LLAB * HIDC];
__device__ float g_part    [NSPLIT * BBAT * LLAB];
__device__ float g_WQe     [3 * HIDC * HIDC];
__device__ float g_WVe     [3 * HIDC * HIDC];

static inline int cdiv(int a, int b) { return (a + b - 1) / b; }

// =====================================================================
// helpers
// =====================================================================
__device__ __forceinline__ uint32_t f2tf(float x) {
    uint32_t r;
    asm("cvt.rna.tf32.f32 %0, %1;" : "=r"(r) : "f"(x));
    return r;
}

__device__ __forceinline__ void mma_tf32(float* c, const uint32_t* a, const uint32_t* b) {
    asm("mma.sync.aligned.m16n8k8.row.col.f32.tf32.tf32.f32 "
        "{%0,%1,%2,%3}, {%4,%5,%6,%7}, {%8,%9}, {%0,%1,%2,%3};"
        : "+f"(c[0]), "+f"(c[1]), "+f"(c[2]), "+f"(c[3])
        : "r"(a[0]), "r"(a[1]), "r"(a[2]), "r"(a[3]), "r"(b[0]), "r"(b[1]));
}

__device__ __forceinline__ void cpa16(void* s, const void* g, bool v) {
    uint32_t sa = (uint32_t)__cvta_generic_to_shared(s);
    int sz = v ? 16 : 0;
    asm volatile("cp.async.cg.shared.global [%0], [%1], 16, %2;" :: "r"(sa), "l"(g), "r"(sz));
}
__device__ __forceinline__ void cp_commit() { asm volatile("cp.async.commit_group;"); }
__device__ __forceinline__ void cp_wait1()  { asm volatile("cp.async.wait_group 1;"); }
__device__ __forceinline__ void cp_wait0()  { asm volatile("cp.async.wait_group 0;"); }

// =====================================================================
// 2-stage cp.async pipelined tf32 GEMM (device body)
// MODE 0: Y = acc (+bias[n]) ; MODE 1: Y = tanh(acc+bias) ; MODE 2: Y = tanh(acc)+res
// TRANS_W=false: Y[m,n]=sum_k X[m,k]*W[n,k] ; true: W[k,n]
// =====================================================================
template<int BM, int BN, int BK, int WM, int WN, int MODE, bool TRANS_W>
__device__ __forceinline__ void tgemm_dev(
    const float* __restrict__ X, const float* __restrict__ W,
    const float* __restrict__ bias, const float* __restrict__ res,
    float* __restrict__ Y,
    int M, int N, int K, int ldx, int ldw, int ldy)
{
    constexpr int NWARP = (BM / WM) * (BN / WN);
    constexpr int NTHR  = NWARP * 32;
    constexpr int LDA   = BK + 4;
    constexpr int LDBN  = BK + 4;
    constexpr int LDBT  = BN + 8;
    constexpr int MI = WM / 16, NI = WN / 8;

    __shared__ float As[2][BM * LDA];
    __shared__ float Bs[2][TRANS_W ? (BK * LDBT) : (BN * LDBN)];

    const int m0 = blockIdx.y * BM, n0 = blockIdx.x * BN;
    const int tid  = threadIdx.x;
    const int lane = tid & 31, wid = tid >> 5;
    const int wN = wid % (BN / WN), wM = wid / (BN / WN);
    const int g = lane >> 2, tg = lane & 3;

    float acc[MI][NI][4];
    #pragma unroll
    for (int i = 0; i < MI; i++)
        #pragma unroll
        for (int j = 0; j < NI; j++)
            #pragma unroll
            for (int r = 0; r < 4; r++) acc[i][j][r] = 0.f;

    const int T = K / BK;

    auto load_tile = [&](int t, int st) {
        int k0 = t * BK;
        #pragma unroll
        for (int c = tid; c < BM * (BK / 4); c += NTHR) {
            int row = c >> 2, kq = (c & 3) * 4;
            bool v = (m0 + row) < M;
            int gr = v ? (m0 + row) : 0;
            cpa16(&As[st][row * LDA + kq], X + (long)gr * ldx + k0 + kq, v);
        }
        if (!TRANS_W) {
            #pragma unroll
            for (int c = tid; c < BN * (BK / 4); c += NTHR) {
                int row = c >> 2, kq = (c & 3) * 4;
                bool v = (n0 + row) < N;
                int gr = v ? (n0 + row) : 0;
                cpa16(&Bs[st][row * LDBN + kq], W + (long)gr * ldw + k0 + kq, v);
            }
        } else {
            #pragma unroll
            for (int c = tid; c < BK * (BN / 4); c += NTHR) {
                int k = c / (BN / 4), nq = (c % (BN / 4)) * 4;
                bool v = (n0 + nq) < N;
                int gc = v ? (n0 + nq) : 0;
                cpa16(&Bs[st][k * LDBT + nq], W + (long)(k0 + k) * ldw + gc, v);
            }
        }
    };

    load_tile(0, 0);
    cp_commit();

    for (int t = 0; t < T; t++) {
        int cur = t & 1;
        if (t + 1 < T) {
            load_tile(t + 1, cur ^ 1);
            cp_commit();
            cp_wait1();
        } else {
            cp_wait0();
        }
        __syncthreads();

        #pragma unroll
        for (int kk = 0; kk < BK; kk += 8) {
            uint32_t a[MI][4], b[NI][2];
            #pragma unroll
            for (int mi = 0; mi < MI; mi++) {
                int mr = wM * WM + mi * 16;
                a[mi][0] = f2tf(As[cur][(mr + g)     * LDA + kk + tg]);
                a[mi][1] = f2tf(As[cur][(mr + g + 8) * LDA + kk + tg]);
                a[mi][2] = f2tf(As[cur][(mr + g)     * LDA + kk + tg + 4]);
                a[mi][3] = f2tf(As[cur][(mr + g + 8) * LDA + kk + tg + 4]);
            }
            #pragma unroll
            for (int ni = 0; ni < NI; ni++) {
                int nc = wN * WN + ni * 8;
                if (!TRANS_W) {
                    b[ni][0] = f2tf(Bs[cur][(nc + g) * LDBN + kk + tg]);
                    b[ni][1] = f2tf(Bs[cur][(nc + g) * LDBN + kk + tg + 4]);
                } else {
                    b[ni][0] = f2tf(Bs[cur][(kk + tg)     * LDBT + nc + g]);
                    b[ni][1] = f2tf(Bs[cur][(kk + tg + 4) * LDBT + nc + g]);
                }
            }
            #pragma unroll
            for (int mi = 0; mi < MI; mi++)
                #pragma unroll
                for (int ni = 0; ni < NI; ni++)
                    mma_tf32(acc[mi][ni], a[mi], b[ni]);
        }
        __syncthreads();
    }

    #pragma unroll
    for (int mi = 0; mi < MI; mi++) {
        #pragma unroll
        for (int ni = 0; ni < NI; ni++) {
            int mr = m0 + wM * WM + mi * 16 + g;
            int nc = n0 + wN * WN + ni * 8 + 2 * tg;
            #pragma unroll
            for (int r = 0; r < 4; r++) {
                int m = mr + (r >> 1) * 8;
                int n = nc + (r & 1);
                if (m >= M || n >= N) continue;
                float v = acc[mi][ni][r];
                if (MODE == 0)      { if (bias) v += bias[n]; }
                else if (MODE == 1) { v = tanhf(v + bias[n]); }
                else if (MODE == 2) { v = tanhf(v) + res[(long)m * ldy + n]; }
                Y[(long)m * ldy + n] = v;
            }
        }
    }
}

template<int BM, int BN, int BK, int WM, int WN, int MODE, bool TRANS_W>
__global__ void __launch_bounds__((BM / WM) * (BN / WN) * 32)
tgemm_g(const float* __restrict__ Xg, const float* __restrict__ Wg,
        const float* __restrict__ bias, float* __restrict__ Yg,
        int M, int N, int K, int ldx, int ldw, int ldy,
        long bsx, long bsw, long bsy)
{
    int bz = blockIdx.z;
    tgemm_dev<BM, BN, BK, WM, WN, MODE, TRANS_W>(
        Xg + bz * bsx, Wg + bz * bsw, bias, nullptr, Yg + bz * bsy,
        M, N, K, ldx, ldw, ldy);
}

// =====================================================================
// Effective weights
// =====================================================================
__global__ void prep_eff(const float* __restrict__ WQ, const float* __restrict__ WV,
                         const float* __restrict__ PA, const float* __restrict__ PM,
                         float* __restrict__ WQe, float* __restrict__ WVe)
{
    int t = blockIdx.x >> 3, h = blockIdx.x & 7;
    const float* W = (blockIdx.y == 0 ? WQ : WV) + (long)t * HIDC * HIDC + (long)h * DHH * HIDC;
    const float* P = (blockIdx.y == 0 ? PA : PM);
    float* O = (blockIdx.y == 0 ? WQe : WVe) + (long)t * HIDC * HIDC + (long)h * DHH * HIDC;

    __shared__ float Ps[DHH][DHH];
    int tid = threadIdx.x;
    for (int i = tid; i < DHH * DHH; i += 256) Ps[i / DHH][i % DHH] = P[i];
    __syncthreads();

    int c = tid;
    float w[DHH];
    #pragma unroll
    for (int d = 0; d < DHH; d++) w[d] = W[(long)d * HIDC + c];
    #pragma unroll
    for (int e = 0; e < DHH; e++) {
        float s = 0.f;
        #pragma unroll
        for (int d = 0; d < DHH; d++) s += Ps[e][d] * w[d];
        O[(long)e * HIDC + c] = s;
    }
}

// =====================================================================
// Fused per-type projections: grid (4, 5, 9), 128 threads
// =====================================================================
__global__ void __launch_bounds__(128)
proj_fused(const float* __restrict__ le,
           const float* __restrict__ WK,
           const float* __restrict__ WQe,
           const float* __restrict__ WVe,
           float* __restrict__ Kb, float* __restrict__ PAQ,
           float* __restrict__ PMV)
{
    int z = blockIdx.z;
    int t = z % 3, which = z / 3;
    int s0 = (t == 0) ? 0 : (t == 1 ? NN1 : NN1 + NN2);
    int cnt = (t == 0) ? NN1 : (t == 1 ? NN2 : NN3);
    if ((int)blockIdx.y * 64 >= cnt) return;
    const float* W = (which == 0 ? WK : (which == 1 ? WQe : WVe)) + (long)t * HIDC * HIDC;
    float* Y = (which == 0 ? Kb : (which == 1 ? PAQ : PMV)) + (long)s0 * HIDC;
    tgemm_dev<64, 64, 16, 32, 32, 0, false>(
        le + (long)s0 * HIDC, W, nullptr, nullptr, Y,
        cnt, HIDC, HIDC, HIDC, HIDC, HIDC);
}

__global__ void __launch_bounds__(128)
wa_fused(const float* __restrict__ Mm, const float* __restrict__ WA,
         float* __restrict__ le)
{
    int t = blockIdx.z;
    int s0 = (t == 0) ? 0 : (t == 1 ? NN1 : NN1 + NN2);
    int cnt = (t == 0) ? NN1 : (t == 1 ? NN2 : NN3);
    if ((int)blockIdx.y * 64 >= cnt) return;
    tgemm_dev<64, 64, 16, 32, 32, 2, false>(
        Mm + (long)s0 * HIDC, WA + (long)t * HIDC * HIDC, nullptr,
        le + (long)s0 * HIDC, le + (long)s0 * HIDC,
        cnt, HIDC, HIDC, HIDC, HIDC, HIDC);
}

// =====================================================================
// Fused HGT attention
// =====================================================================
__global__ void __launch_bounds__(256)
attn_fused(const float* __restrict__ paq, const float* __restrict__ Kb,
           const float* __restrict__ pmv, const int* __restrict__ amask,
           float* __restrict__ Mout)
{
    extern __shared__ float Ss[];
    __shared__ float invs[32];
    const float scale = 0.17677669529663687f;

    const int qt = blockIdx.x, h = blockIdx.y;
    const int q0 = qt * 32, hd = h * DHH;
    const int tid = threadIdx.x, lane = tid & 31, wid = tid >> 5;

    {
        int gq = q0 + lane;
        int qc = (gq < LLAB) ? gq : (LLAB - 1);
        float qreg[DHH];
        #pragma unroll
        for (int d = 0; d < DHH; d++) qreg[d] = paq[(long)qc * HIDC + hd + d];

        int kend = wid * 75 + 75;
        for (int k = wid * 75; k < kend; k++) {
            float kv = Kb[(long)k * HIDC + hd + lane];
            float s = 0.f;
            #pragma unroll
            for (int d = 0; d < DHH; d++)
                s = fmaf(qreg[d], __shfl_sync(0xffffffffu, kv, d), s);
            Ss[lane * 601 + k] = s;
        }
    }
    __syncthreads();

    #pragma unroll
    for (int rr = 0; rr < 4; rr++) {
        int q = wid * 4 + rr;
        int gq = q0 + q;
        if (gq >= LLAB) continue;
        bool qb1 = (gq < NN1), qb3 = (gq >= NN1 + NN2);

        float mx = -INFINITY;
        for (int k = lane; k < LLAB; k += 32) {
            bool kb1 = (k < NN1), kb3 = (k >= NN1 + NN2);
            bool Z = (qb1 && kb3) || (qb3 && kb1);
            float mk = (amask[(long)gq * LLAB + k] == 0) ? -INFINITY : 0.f;
            float v = (Z ? 0.f : Ss[q * 601 + k] * scale) + mk;
            Ss[q * 601 + k] = v;
            mx = fmaxf(mx, v);
        }
        #pragma unroll
        for (int o = 16; o; o >>= 1) mx = fmaxf(mx, __shfl_xor_sync(0xffffffffu, mx, o));

        float sum = 0.f;
        for (int k = lane; k < LLAB; k += 32) {
            bool kb1 = (k < NN1), kb3 = (k >= NN1 + NN2);
            bool Z = (qb1 && kb3) || (qb3 && kb1);
            float e = expf(Ss[q * 601 + k] - mx);
            sum += e;
            Ss[q * 601 + k] = Z ? 0.f : e;
        }
        #pragma unroll
        for (int o = 16; o; o >>= 1) sum += __shfl_xor_sync(0xffffffffu, sum, o);
        if (lane == 0) invs[q] = 1.f / sum;
    }
    __syncthreads();

    {
        float acc0 = 0.f, acc1 = 0.f, acc2 = 0.f, acc3 = 0.f;
        const int qb = wid * 4;
        for (int k = 0; k < LLAB; k += 2) {
            float pv0 = pmv[(long)k * HIDC + hd + lane];
            float pv1 = pmv[(long)(k + 1) * HIDC + hd + lane];
            acc0 = fmaf(Ss[(qb + 0) * 601 + k], pv0, acc0);
            acc1 = fmaf(Ss[(qb + 1) * 601 + k], pv0, acc1);
            acc2 = fmaf(Ss[(qb + 2) * 601 + k], pv0, acc2);
            acc3 = fmaf(Ss[(qb + 3) * 601 + k], pv0, acc3);
            acc0 = fmaf(Ss[(qb + 0) * 601 + k + 1], pv1, acc0);
            acc1 = fmaf(Ss[(qb + 1) * 601 + k + 1], pv1, acc1);
            acc2 = fmaf(Ss[(qb + 2) * 601 + k + 1], pv1, acc2);
            acc3 = fmaf(Ss[(qb + 3) * 601 + k + 1], pv1, acc3);
        }
        float accs[4] = {acc0, acc1, acc2, acc3};
        #pragma unroll
        for (int rr = 0; rr < 4; rr++) {
            int gq = q0 + qb + rr;
            if (gq < LLAB)
                Mout[(long)gq * HIDC + hd + lane] = accs[rr] * invs[qb + rr];
        }
    }
}

// ---------------- pooling softmax over S with pad mask (l-range version) ----------------
__global__ void pool_softmax(float* __restrict__ aw, const int* __restrict__ tok, int l0)
{
    const int l = l0 + blockIdx.x, b = blockIdx.y;
    float* row = aw + ((long)b * LLAB + l) * SSEQ;
    const int* t = tok + (long)b * SSEQ;

    __shared__ float buf[SSEQ];
    __shared__ float red[33];
    const int tid = threadIdx.x;   // 256

    float mx = -INFINITY;
    for (int s = tid; s < SSEQ; s += 256) {
        int tv = t[s];
        bool bad = (tv == 0) || (tv == 101) || (tv == 102);
        float v = row[s] + (bad ? -INFINITY : 0.f);
        buf[s] = v;
        mx = fmaxf(mx, v);
    }
    for (int o = 16; o; o >>= 1) mx = fmaxf(mx, __shfl_xor_sync(0xffffffffu, mx, o));
    if ((tid & 31) == 0) red[tid >> 5] = mx;
    __syncthreads();
    if (tid < 32) {
        float v = (tid < 8) ? red[tid] : -INFINITY;
        for (int o = 16; o; o >>= 1) v = fmaxf(v, __shfl_xor_sync(0xffffffffu, v, o));
        if (tid == 0) red[32] = v;
    }
    __syncthreads();
    mx = red[32];
    __syncthreads();

    float sum = 0.f;
    for (int s = tid; s < SSEQ; s += 256) {
        float e = expf(buf[s] - mx);
        buf[s] = e;
        sum += e;
    }
    for (int o = 16; o; o >>= 1) sum += __shfl_xor_sync(0xffffffffu, sum, o);
    if ((tid & 31) == 0) red[tid >> 5] = sum;
    __syncthreads();
    if (tid < 32) {
        float v = (tid < 8) ? red[tid] : 0.f;
        for (int o = 16; o; o >>= 1) v += __shfl_xor_sync(0xffffffffu, v, o);
        if (tid == 0) red[32] = v;
    }
    __syncthreads();
    float inv = 1.f / red[32];

    for (int s = tid; s < SSEQ; s += 256) row[s] = buf[s] * inv;
}

// ---------------- final split-K reduce + sigmoid ----------------
__global__ void final_reduce(const float* __restrict__ part,
                             const float* __restrict__ bout,
                             float* __restrict__ out)
{
    int i = blockIdx.x * blockDim.x + threadIdx.x;
    if (i >= BBAT * LLAB) return;
    int l = i % LLAB;
    float s = bout[l];
    #pragma unroll
    for (int z = 0; z < NSPLIT; z++) s += part[z * (BBAT * LLAB) + i];
    out[i] = 1.f / (1.f + expf(-s));
}

// ---------------- streams for overlap (created at static init) ----------------
struct HgtStreams {
    cudaStream_t s_te = nullptr;
    cudaEvent_t ev_fork = nullptr, ev_te = nullptr, ev_le = nullptr, ev_c1 = nullptr;
    HgtStreams() {
        if (cudaStreamCreateWithFlags(&s_te, cudaStreamNonBlocking) != cudaSuccess) { s_te = nullptr; return; }
        if (cudaEventCreateWithFlags(&ev_fork, cudaEventDisableTiming) != cudaSuccess) { s_te = nullptr; return; }
        if (cudaEventCreateWithFlags(&ev_te, cudaEventDisableTiming) != cudaSuccess) { s_te = nullptr; return; }
        if (cudaEventCreateWithFlags(&ev_le, cudaEventDisableTiming) != cudaSuccess) { s_te = nullptr; return; }
        if (cudaEventCreateWithFlags(&ev_c1, cudaEventDisableTiming) != cudaSuccess) { s_te = nullptr; return; }
    }
};
static HgtStreams g_hs;

// ---------------- host orchestration ----------------
extern "C" void kernel_launch(void* const* d_in, const int* in_sizes, int n_in,
                              void* d_out, int out_size)
{
    const int*   inputs      = (const int*)  d_in[0];
    const float* text_hidden = (const float*)d_in[1];
    const float* label_feat  = (const float*)d_in[2];
    const int*   amask       = (const int*)  d_in[3];
    const float* Wt   = (const float*)d_in[4];
    const float* bt   = (const float*)d_in[5];
    const float* Wl   = (const float*)d_in[6];
    const float* bl   = (const float*)d_in[7];
    const float* WK   = (const float*)d_in[8];
    const float* WQ   = (const float*)d_in[9];
    const float* WV   = (const float*)d_in[10];
    const float* PA   = (const float*)d_in[11];
    const float* PM   = (const float*)d_in[12];
    const float* WA   = (const float*)d_in[13];
    const float* Wout = (const float*)d_in[14];
    const float* bout = (const float*)d_in[15];
    float* out = (float*)d_out;

    float *te, *le, *Kb, *paq, *pmv, *mm, *aw, *feat, *part, *wqe, *wve;
    cudaGetSymbolAddress((void**)&te,   g_text_enc);
    cudaGetSymbolAddress((void**)&le,   g_le);
    cudaGetSymbolAddress((void**)&Kb,   g_Kb);
    cudaGetSymbolAddress((void**)&paq,  g_PAQ);
    cudaGetSymbolAddress((void**)&pmv,  g_PMV);
    cudaGetSymbolAddress((void**)&mm,   g_M);
    cudaGetSymbolAddress((void**)&aw,   g_aw);
    cudaGetSymbolAddress((void**)&feat, g_feat);
    cudaGetSymbolAddress((void**)&part, g_part);
    cudaGetSymbolAddress((void**)&wqe,  g_WQe);
    cudaGetSymbolAddress((void**)&wve,  g_WVe);

    cudaFuncSetAttribute(attn_fused, cudaFuncAttributeMaxDynamicSharedMemorySize, ATTN_SMEM);

    const bool ovl = (g_hs.s_te != nullptr);
    cudaStream_t ste = ovl ? g_hs.s_te : (cudaStream_t)0;
    const int KS = (LLAB * HIDC) / NSPLIT;   // 2400

    // ---- fork: text_enc on side stream, label chain on main stream ----
    if (ovl) {
        cudaEventRecord(g_hs.ev_fork, 0);
        cudaStreamWaitEvent(g_hs.s_te, g_hs.ev_fork, 0);
    }

    // text_enc = tanh(text_hidden @ Wt^T + bt)   [16384, 256] K=768  (side)
    tgemm_g<128, 128, 16, 64, 32, 1, false><<<dim3(cdiv(HIDC, 128), cdiv(BBAT * SSEQ, 128), 1), 256, 0, ste>>>(
        text_hidden, Wt, bt, te,
        BBAT * SSEQ, HIDC, DBERT, DBERT, DBERT, HIDC, 0, 0, 0);
    if (ovl) cudaEventRecord(g_hs.ev_te, g_hs.s_te);

    // ---- label-side chain on main stream ----
    prep_eff<<<dim3(24, 2), 256>>>(WQ, WV, PA, PM, wqe, wve);

    tgemm_g<128, 128, 16, 64, 32, 0, false><<<dim3(cdiv(HIDC, 128), cdiv(LLAB, 128), 1), 256>>>(
        label_feat, Wl, bl, le,
        LLAB, HIDC, DBERT, DBERT, DBERT, HIDC, 0, 0, 0);

    for (int layer = 0; layer < 2; layer++) {
        proj_fused<<<dim3(cdiv(HIDC, 64), cdiv(NN3, 64), 9), 128>>>(
            le, WK, wqe, wve, Kb, paq, pmv);

        attn_fused<<<dim3(cdiv(LLAB, 32), NHEAD), 256, ATTN_SMEM>>>(
            paq, Kb, pmv, amask, mm);

        wa_fused<<<dim3(cdiv(HIDC, 64), cdiv(NN3, 64), 3), 128>>>(mm, WA, le);
    }
    if (ovl) cudaEventRecord(g_hs.ev_le, 0);     // le final

    // ---- two label-half pooling chains ----
    // chain0 (main, l < 300): needs te
    if (ovl) cudaStreamWaitEvent(0, g_hs.ev_te, 0);
    // chain1 (side, l >= 300): side already produced te; needs le
    if (ovl) cudaStreamWaitEvent(g_hs.s_te, g_hs.ev_le, 0);

    const int L0 = LSPLIT, L1 = LLAB - LSPLIT;   // 300 / 300

    // ---- chain0 on main stream ----
    tgemm_g<128, 128, 16, 64, 32, 0, false><<<dim3(cdiv(SSEQ, 128), cdiv(L0, 128), BBAT), 256>>>(
        le, te, nullptr, aw,
        L0, SSEQ, HIDC, HIDC, HIDC, SSEQ,
        0, (long)SSEQ * HIDC, (long)LLAB * SSEQ);
    pool_softmax<<<dim3(L0, BBAT), 256>>>(aw, inputs, 0);
    tgemm_g<128, 128, 16, 64, 32, 0, true><<<dim3(cdiv(HIDC, 128), cdiv(L0, 128), BBAT), 256>>>(
        aw, te, nullptr, feat,
        L0, HIDC, SSEQ, SSEQ, HIDC, HIDC,
        (long)LLAB * SSEQ, (long)SSEQ * HIDC, (long)LLAB * HIDC);
    // final half 0: z in [0, 32) -> k in [0, 76800) -> labels [0, 300)
    tgemm_g<32, 128, 16, 16, 32, 0, false><<<dim3(cdiv(LLAB, 128), 1, ZSPLIT), 256>>>(
        feat, Wout, nullptr, part,
        BBAT, LLAB, KS,
        LLAB * HIDC, LLAB * HIDC, LLAB,
        (long)KS, (long)KS, (long)BBAT * LLAB);

    // ---- chain1 on side stream ----
    if (ovl) {
        tgemm_g<128, 128, 16, 64, 32, 0, false><<<dim3(cdiv(SSEQ, 128), cdiv(L1, 128), BBAT), 256, 0, ste>>>(
            le + (long)LSPLIT * HIDC, te, nullptr, aw + (long)LSPLIT * SSEQ,
            L1, SSEQ, HIDC, HIDC, HIDC, SSEQ,
            0, (long)SSEQ * HIDC, (long)LLAB * SSEQ);
        pool_softmax<<<dim3(L1, BBAT), 256, 0, ste>>>(aw, inputs, LSPLIT);
        tgemm_g<128, 128, 16, 64, 32, 0, true><<<dim3(cdiv(HIDC, 128), cdiv(L1, 128), BBAT), 256, 0, ste>>>(
            aw + (long)LSPLIT * SSEQ, te, nullptr, feat + (long)LSPLIT * HIDC,
            L1, HIDC, SSEQ, SSEQ, HIDC, HIDC,
            (long)LLAB * SSEQ, (long)SSEQ * HIDC, (long)LLAB * HIDC);
        // final half 1: z in [32, 64) -> k in [76800, 153600) -> labels [300, 600)
        tgemm_g<32, 128, 16, 16, 32, 0, false><<<dim3(cdiv(LLAB, 128), 1, NSPLIT - ZSPLIT), 256, 0, ste>>>(
            feat + (long)ZSPLIT * KS, Wout + (long)ZSPLIT * KS, nullptr,
            part + (long)ZSPLIT * BBAT * LLAB,
            BBAT, LLAB, KS,
            LLAB * HIDC, LLAB * HIDC, LLAB,
            (long)KS, (long)KS, (long)BBAT * LLAB);
        cudaEventRecord(g_hs.ev_c1, g_hs.s_te);
        cudaStreamWaitEvent(0, g_hs.ev_c1, 0);
    } else {
        // fallback: serial chain1 on main stream
        tgemm_g<128, 128, 16, 64, 32, 0, false><<<dim3(cdiv(SSEQ, 128), cdiv(L1, 128), BBAT), 256>>>(
            le + (long)LSPLIT * HIDC, te, nullptr, aw + (long)LSPLIT * SSEQ,
            L1, SSEQ, HIDC, HIDC, HIDC, SSEQ,
            0, (long)SSEQ * HIDC, (long)LLAB * SSEQ);
        pool_softmax<<<dim3(L1, BBAT), 256>>>(aw, inputs, LSPLIT);
        tgemm_g<128, 128, 16, 64, 32, 0, true><<<dim3(cdiv(HIDC, 128), cdiv(L1, 128), BBAT), 256>>>(
            aw + (long)LSPLIT * SSEQ, te, nullptr, feat + (long)LSPLIT * HIDC,
            L1, HIDC, SSEQ, SSEQ, HIDC, HIDC,
            (long)LLAB * SSEQ, (long)SSEQ * HIDC, (long)LLAB * HIDC);
        tgemm_g<32, 128, 16, 16, 32, 0, false><<<dim3(cdiv(LLAB, 128), 1, NSPLIT - ZSPLIT), 256>>>(
            feat + (long)ZSPLIT * KS, Wout + (long)ZSPLIT * KS, nullptr,
            part + (long)ZSPLIT * BBAT * LLAB,
            BBAT, LLAB, KS,
            LLAB * HIDC, LLAB * HIDC, LLAB,
            (long)KS, (long)KS, (long)BBAT * LLAB);
    }

    final_reduce<<<cdiv(BBAT * LLAB, 256), 256>>>(part, bout, out);
}